// round 6
// baseline (speedup 1.0000x reference)
#include <cuda_runtime.h>
#include <math.h>

// Problem constants
#define BATCH 16
#define CHAN  256
#define HDIM  96
#define HW    9216           // 96*96
#define SCALE 0.0625f        // 1/sqrt(256)

// Scratch for q,k,v: [3][B][C][HW] floats = 453 MB (device global: allocation-free)
__device__ float g_qkv[3ULL * BATCH * CHAN * HW];

// ---------------------------------------------------------------------------
// Kernel 1: fused QKV projection.
// For batch b:  Q = Wq @ X + bq, etc.  (M=256 per matrix, N=9216, K=256)
// Classic 128x128x8 smem-tiled SGEMM, 256 threads, 8x8 microtile.
// grid = (72, 6, 16): x = N tiles, y = stacked-M tiles (768/128), z = batch
// ---------------------------------------------------------------------------
#define BM 128
#define BN 128
#define BK 8

__global__ __launch_bounds__(256, 2)
void proj_kernel(const float* __restrict__ X,
                 const float* __restrict__ Wq, const float* __restrict__ bq,
                 const float* __restrict__ Wk, const float* __restrict__ bk,
                 const float* __restrict__ Wv, const float* __restrict__ bv)
{
    const int b     = blockIdx.z;
    const int tileM = blockIdx.y;            // 0..5
    const int mat   = tileM >> 1;            // 0=q, 1=k, 2=v
    const int mBase = (tileM & 1) * BM;      // 0 or 128 inside the matrix
    const int nBase = blockIdx.x * BN;

    const float* W    = (mat == 0) ? Wq : (mat == 1) ? Wk : Wv;
    const float* bias = (mat == 0) ? bq : (mat == 1) ? bk : bv;
    const float* Xb   = X + (size_t)b * CHAN * HW;

    __shared__ float As[BK][BM];
    __shared__ float Bs[BK][BN];

    const int tid = threadIdx.x;
    const int tx  = tid & 15;      // 0..15  -> n microtile
    const int ty  = tid >> 4;      // 0..15  -> m microtile

    // A-tile load mapping: 128 rows x 8 cols = 256 float4 (along k)
    const int aRow  = tid >> 1;          // 0..127
    const int aCol4 = (tid & 1) * 4;     // 0 or 4
    // B-tile load mapping: 8 rows x 128 cols = 256 float4 (along n)
    const int bRow  = tid >> 5;          // 0..7
    const int bCol  = (tid & 31) * 4;    // 0..124

    float acc[8][8];
#pragma unroll
    for (int i = 0; i < 8; i++)
#pragma unroll
        for (int j = 0; j < 8; j++) acc[i][j] = 0.0f;

    for (int k0 = 0; k0 < CHAN; k0 += BK) {
        float4 av = *(const float4*)&W[(size_t)(mBase + aRow) * CHAN + k0 + aCol4];
        As[aCol4 + 0][aRow] = av.x;
        As[aCol4 + 1][aRow] = av.y;
        As[aCol4 + 2][aRow] = av.z;
        As[aCol4 + 3][aRow] = av.w;
        *(float4*)&Bs[bRow][bCol] =
            *(const float4*)&Xb[(size_t)(k0 + bRow) * HW + nBase + bCol];
        __syncthreads();

#pragma unroll
        for (int kk = 0; kk < BK; kk++) {
            float a[8], bb[8];
            *(float4*)&a[0]  = *(float4*)&As[kk][ty * 8];
            *(float4*)&a[4]  = *(float4*)&As[kk][ty * 8 + 4];
            *(float4*)&bb[0] = *(float4*)&Bs[kk][tx * 8];
            *(float4*)&bb[4] = *(float4*)&Bs[kk][tx * 8 + 4];
#pragma unroll
            for (int i = 0; i < 8; i++)
#pragma unroll
                for (int j = 0; j < 8; j++)
                    acc[i][j] = fmaf(a[i], bb[j], acc[i][j]);
        }
        __syncthreads();
    }

    // Store to scratch: g_qkv[mat][b][d][s]
    float* outBase = g_qkv + ((size_t)mat * BATCH + b) * CHAN * HW;
#pragma unroll
    for (int i = 0; i < 8; i++) {
        const int d  = mBase + ty * 8 + i;
        const float bv = bias[d];
        size_t off = (size_t)d * HW + nBase + tx * 8;
        float4 v0 = { acc[i][0] + bv, acc[i][1] + bv, acc[i][2] + bv, acc[i][3] + bv };
        float4 v1 = { acc[i][4] + bv, acc[i][5] + bv, acc[i][6] + bv, acc[i][7] + bv };
        *(float4*)&outBase[off]     = v0;
        *(float4*)&outBase[off + 4] = v1;
    }
}

// ---------------------------------------------------------------------------
// Kernel 2: per-(b,c) attention plane.
// scores = (q @ k^T) * SCALE ; softmax rows ; attended = weights @ v ; +fmap
// One block per (b,c): 256 threads, 6x6 microtile over 96x96, smem pitch 97.
// Dynamic smem: 3 * 96 * 97 * 4 = 111744 bytes  (q|v buffer, k buffer, scores)
// ---------------------------------------------------------------------------
#define PIT 97
#define ATTN_SMEM (3 * HDIM * PIT * 4)

__global__ __launch_bounds__(256)
void attn_kernel(const float* __restrict__ fmap, float* __restrict__ out)
{
    extern __shared__ float sm[];
    float* qs = sm;                   // later reused for v
    float* ks = sm + HDIM * PIT;
    float* sc = sm + 2 * HDIM * PIT;

    const int bc = blockIdx.x;        // b*256 + c
    const size_t plane    = (size_t)bc * HW;
    const size_t matStride = (size_t)BATCH * CHAN * HW;
    const float* qg = g_qkv + plane;
    const float* kg = g_qkv + matStride + plane;
    const float* vg = g_qkv + 2 * matStride + plane;

    const int tid = threadIdx.x;

    // Load q and k planes into smem (pitch 97)
    for (int i = tid; i < HW; i += 256) {
        int h = i / HDIM, w = i - h * HDIM;
        qs[h * PIT + w] = qg[i];
        ks[h * PIT + w] = kg[i];
    }
    __syncthreads();

    const int tx = tid & 15;          // g / w microtile
    const int ty = tid >> 4;          // h microtile
    const int h0 = ty * 6;
    const int g0 = tx * 6;

    // Phase 1: scores = q @ k^T * SCALE
    {
        float acc[6][6];
#pragma unroll
        for (int i = 0; i < 6; i++)
#pragma unroll
            for (int j = 0; j < 6; j++) acc[i][j] = 0.0f;

        for (int w = 0; w < HDIM; w++) {
            float a[6], bb[6];
#pragma unroll
            for (int j = 0; j < 6; j++) a[j]  = qs[(h0 + j) * PIT + w];
#pragma unroll
            for (int j = 0; j < 6; j++) bb[j] = ks[(g0 + j) * PIT + w];
#pragma unroll
            for (int i = 0; i < 6; i++)
#pragma unroll
                for (int j = 0; j < 6; j++)
                    acc[i][j] = fmaf(a[i], bb[j], acc[i][j]);
        }
#pragma unroll
        for (int i = 0; i < 6; i++)
#pragma unroll
            for (int j = 0; j < 6; j++)
                sc[(h0 + i) * PIT + g0 + j] = acc[i][j] * SCALE;
    }
    __syncthreads();

    // Phase 2: row softmax (8 warps x 12 rows each)
    {
        const int warp = tid >> 5, lane = tid & 31;
        for (int r = warp; r < HDIM; r += 8) {
            float m = -1e30f;
            for (int j = lane; j < HDIM; j += 32) m = fmaxf(m, sc[r * PIT + j]);
#pragma unroll
            for (int o = 16; o; o >>= 1) m = fmaxf(m, __shfl_xor_sync(0xffffffffu, m, o));
            float e[3]; float s = 0.0f;
            {
                int t = 0;
                for (int j = lane; j < HDIM; j += 32, t++) {
                    e[t] = __expf(sc[r * PIT + j] - m);
                    s += e[t];
                }
            }
#pragma unroll
            for (int o = 16; o; o >>= 1) s += __shfl_xor_sync(0xffffffffu, s, o);
            const float inv = 1.0f / s;
            {
                int t = 0;
                for (int j = lane; j < HDIM; j += 32, t++)
                    sc[r * PIT + j] = e[t] * inv;
            }
        }
    }
    __syncthreads();

    // Load v into the q buffer
    for (int i = tid; i < HW; i += 256) {
        int h = i / HDIM, w = i - h * HDIM;
        qs[h * PIT + w] = vg[i];
    }
    __syncthreads();

    // Phase 3: attended = weights @ v ; out = fmap + attended
    {
        float acc[6][6];
#pragma unroll
        for (int i = 0; i < 6; i++)
#pragma unroll
            for (int j = 0; j < 6; j++) acc[i][j] = 0.0f;

        const int w0 = g0;  // tx*6 now indexes w
        for (int g = 0; g < HDIM; g++) {
            float a[6], bb[6];
#pragma unroll
            for (int j = 0; j < 6; j++) a[j]  = sc[(h0 + j) * PIT + g];
#pragma unroll
            for (int j = 0; j < 6; j++) bb[j] = qs[g * PIT + w0 + j];
#pragma unroll
            for (int i = 0; i < 6; i++)
#pragma unroll
                for (int j = 0; j < 6; j++)
                    acc[i][j] = fmaf(a[i], bb[j], acc[i][j]);
        }

        const float* fm = fmap + plane;
        float* og = out + plane;
#pragma unroll
        for (int i = 0; i < 6; i++)
#pragma unroll
            for (int j = 0; j < 6; j++) {
                int idx = (h0 + i) * HDIM + w0 + j;
                og[idx] = fm[idx] + acc[i][j];
            }
    }
}

// ---------------------------------------------------------------------------
// Launch
// Inputs (metadata order): feature, feature_map, Wq, bq, Wk, bk, Wv, bv
// ---------------------------------------------------------------------------
extern "C" void kernel_launch(void* const* d_in, const int* in_sizes, int n_in,
                              void* d_out, int out_size)
{
    const float* feature  = (const float*)d_in[0];
    const float* fmap     = (const float*)d_in[1];
    const float* Wq       = (const float*)d_in[2];
    const float* bq       = (const float*)d_in[3];
    const float* Wk       = (const float*)d_in[4];
    const float* bk       = (const float*)d_in[5];
    const float* Wv       = (const float*)d_in[6];
    const float* bv       = (const float*)d_in[7];
    float* out            = (float*)d_out;

    // Attention kernel needs 111744 B of dynamic smem (> 48 KB default).
    // Idempotent host-side call; executes immediately, not captured.
    cudaFuncSetAttribute(attn_kernel,
                         cudaFuncAttributeMaxDynamicSharedMemorySize,
                         ATTN_SMEM);

    dim3 g1(HW / BN, 6, BATCH);   // (72, 6, 16)
    proj_kernel<<<g1, 256>>>(feature, Wq, bq, Wk, bk, Wv, bv);

    attn_kernel<<<BATCH * CHAN, 256, ATTN_SMEM>>>(fmap, out);
}

// round 8
// speedup vs baseline: 1.9826x; 1.9826x over previous
#include <cuda_runtime.h>
#include <math.h>
#include <stdint.h>

// Problem constants
#define BATCH 16
#define CHAN  256
#define HDIM  96
#define HW    9216           // 96*96
#define SCALE 0.0625f        // 1/sqrt(256)

// Scratch for q,k,v: [3][B][C][HW] floats = 453 MB (device global: allocation-free)
__device__ float g_qkv[3ULL * BATCH * CHAN * HW];

// ===========================================================================
// Helpers (sm_100 baseline: mma.sync tf32 + cp.async, NO tcgen05)
// ===========================================================================
__device__ __forceinline__ uint32_t smem_u32(const void* p) {
    uint32_t a;
    asm("{ .reg .u64 t; cvta.to.shared.u64 t, %1; cvt.u32.u64 %0, t; }"
        : "=r"(a) : "l"(p));
    return a;
}
__device__ __forceinline__ uint32_t f2tf32(float f) {
    uint32_t r;
    asm("cvt.rna.tf32.f32 %0, %1;" : "=r"(r) : "f"(f));
    return r;
}
#define CP_ASYNC16(dst, src) \
    asm volatile("cp.async.cg.shared.global [%0], [%1], 16;" :: "r"(dst), "l"(src))
#define CP_COMMIT()  asm volatile("cp.async.commit_group;" ::: "memory")
#define CP_WAIT(N)   asm volatile("cp.async.wait_group %0;" :: "n"(N) : "memory")

// D += A@B, m16n8k8 tf32
#define MMA_TF32(c, a, b)                                                      \
    asm volatile(                                                              \
        "mma.sync.aligned.m16n8k8.row.col.f32.tf32.tf32.f32 "                  \
        "{%0,%1,%2,%3}, {%4,%5,%6,%7}, {%8,%9}, {%0,%1,%2,%3};"                \
        : "+f"((c)[0]), "+f"((c)[1]), "+f"((c)[2]), "+f"((c)[3])               \
        : "r"((a)[0]), "r"((a)[1]), "r"((a)[2]), "r"((a)[3]),                  \
          "r"((b)[0]), "r"((b)[1]))

// ===========================================================================
// Kernel 1: QKV projection via mma.sync tf32.
// Per CTA: D[128 d][128 px] = W[128][256] @ X[256][128 px] + bias.
// 256 thr = 8 warps (2x4), warp tile 64x32 (4x4 frags of 16x8).
// K: 8 chunks of 32, cp.async double-buffered.
// SMEM (dynamic): A[2][128][36] f32, B[2][32][136] f32 -> 71680 B.
//   A-frag LDS banks = 4r+c (distinct); B-frag banks = 8k+n (distinct).
// grid = (72, 6, 16)
// ===========================================================================
#define PA 36          // A pitch (floats)
#define PB 136         // B pitch (floats)
#define A_FL (128 * PA)       // 4608 floats per A buffer
#define B_FL (32 * PB)        // 4352 floats per B buffer
#define B_BASE (2 * A_FL)     // float offset of B region
#define PROJ_SMEM ((2 * A_FL + 2 * B_FL) * 4)   // 71680 B

__global__ __launch_bounds__(256)
void proj_tc(const float* __restrict__ X,
             const float* __restrict__ Wq, const float* __restrict__ bq,
             const float* __restrict__ Wk, const float* __restrict__ bk,
             const float* __restrict__ Wv, const float* __restrict__ bv)
{
    extern __shared__ float dsm[];
    const uint32_t sb = smem_u32(dsm);

    const int tid  = threadIdx.x;
    const int wid  = tid >> 5;
    const int lane = tid & 31;
    const int wm   = wid & 1;        // warp m (0..1) -> 64 rows
    const int wn   = wid >> 1;       // warp n (0..3) -> 32 cols
    const int gq   = lane >> 2;      // groupID
    const int tq   = lane & 3;       // threadID in group

    const int b     = blockIdx.z;
    const int tileM = blockIdx.y;
    const int mat   = tileM >> 1;
    const int mBase = (tileM & 1) * 128;
    const int s0    = blockIdx.x * 128;

    const float* W    = (mat == 0) ? Wq : (mat == 1) ? Wk : Wv;
    const float* bias = (mat == 0) ? bq : (mat == 1) ? bk : bv;
    const float* Xb   = X + (size_t)b * CHAN * HW;

    float acc[4][4][4];
#pragma unroll
    for (int i = 0; i < 4; i++)
#pragma unroll
        for (int j = 0; j < 4; j++)
#pragma unroll
            for (int r = 0; r < 4; r++) acc[i][j][r] = 0.0f;

    // ---- async-load one 32-wide K chunk into buffer (c & 1) ----
    auto issue_chunk = [&](int c) {
        const int buf = c & 1;
        const int k0  = c * 32;
        const uint32_t aBase = sb + (uint32_t)(buf * A_FL) * 4;
        const uint32_t bBase = sb + (uint32_t)(B_BASE + buf * B_FL) * 4;
#pragma unroll
        for (int i = 0; i < 4; i++) {
            const int f = tid + i * 256;           // 0..1023 float4s
            // A: 128 rows x 8 float4 (k)
            {
                const int row = f >> 3, cv = f & 7;
                CP_ASYNC16(aBase + (uint32_t)(row * PA + cv * 4) * 4,
                           W + (size_t)(mBase + row) * CHAN + k0 + cv * 4);
            }
            // B: 32 rows (k) x 32 float4 (n)
            {
                const int k = f >> 5, cv = f & 31;
                CP_ASYNC16(bBase + (uint32_t)(k * PB + cv * 4) * 4,
                           Xb + (size_t)(k0 + k) * HW + s0 + cv * 4);
            }
        }
    };

    issue_chunk(0);
    CP_COMMIT();

    for (int c = 0; c < 8; c++) {
        if (c < 7) {
            issue_chunk(c + 1);
            CP_COMMIT();
            CP_WAIT(1);
        } else {
            CP_WAIT(0);
        }
        __syncthreads();

        const float* As = dsm + (c & 1) * A_FL;
        const float* Bs = dsm + B_BASE + (c & 1) * B_FL;

#pragma unroll
        for (int kk = 0; kk < 4; kk++) {
            const int kb = kk * 8;
            uint32_t afr[4][4];
#pragma unroll
            for (int mi = 0; mi < 4; mi++) {
                const int r = wm * 64 + mi * 16 + gq;
                const int cc = kb + tq;
                afr[mi][0] = f2tf32(As[r * PA + cc]);
                afr[mi][1] = f2tf32(As[(r + 8) * PA + cc]);
                afr[mi][2] = f2tf32(As[r * PA + cc + 4]);
                afr[mi][3] = f2tf32(As[(r + 8) * PA + cc + 4]);
            }
            uint32_t bfr[4][2];
#pragma unroll
            for (int nj = 0; nj < 4; nj++) {
                const int n = wn * 32 + nj * 8 + gq;
                bfr[nj][0] = f2tf32(Bs[(kb + tq) * PB + n]);
                bfr[nj][1] = f2tf32(Bs[(kb + 4 + tq) * PB + n]);
            }
#pragma unroll
            for (int mi = 0; mi < 4; mi++)
#pragma unroll
                for (int nj = 0; nj < 4; nj++)
                    MMA_TF32(acc[mi][nj], afr[mi], bfr[nj]);
        }
        __syncthreads();
    }

    // ---- epilogue: bias + direct float2 stores (full 32B sectors) ----
    float* outP = g_qkv + ((size_t)mat * BATCH + b) * CHAN * HW;
#pragma unroll
    for (int mi = 0; mi < 4; mi++) {
        const int r0 = mBase + wm * 64 + mi * 16 + gq;
        const float bv0 = bias[r0];
        const float bv1 = bias[r0 + 8];
#pragma unroll
        for (int nj = 0; nj < 4; nj++) {
            const int col = s0 + wn * 32 + nj * 8 + 2 * tq;
            float2 v0 = { acc[mi][nj][0] + bv0, acc[mi][nj][1] + bv0 };
            float2 v1 = { acc[mi][nj][2] + bv1, acc[mi][nj][3] + bv1 };
            *(float2*)&outP[(size_t)r0 * HW + col]       = v0;
            *(float2*)&outP[(size_t)(r0 + 8) * HW + col] = v1;
        }
    }
}

// ---------------------------------------------------------------------------
// Kernel 2: per-(b,c) attention plane (unchanged fp32 path, 572 us).
// ---------------------------------------------------------------------------
#define PIT 97
#define ATTN_SMEM (3 * HDIM * PIT * 4)

__global__ __launch_bounds__(256)
void attn_kernel(const float* __restrict__ fmap, float* __restrict__ out)
{
    extern __shared__ float sm[];
    float* qs = sm;
    float* ks = sm + HDIM * PIT;
    float* sc = sm + 2 * HDIM * PIT;

    const int bc = blockIdx.x;
    const size_t plane     = (size_t)bc * HW;
    const size_t matStride = (size_t)BATCH * CHAN * HW;
    const float* qg = g_qkv + plane;
    const float* kg = g_qkv + matStride + plane;
    const float* vg = g_qkv + 2 * matStride + plane;

    const int tid = threadIdx.x;

    for (int i = tid; i < HW; i += 256) {
        int h = i / HDIM, w = i - h * HDIM;
        qs[h * PIT + w] = qg[i];
        ks[h * PIT + w] = kg[i];
    }
    __syncthreads();

    const int tx = tid & 15;
    const int ty = tid >> 4;
    const int h0 = ty * 6;
    const int g0 = tx * 6;

    {
        float acc[6][6];
#pragma unroll
        for (int i = 0; i < 6; i++)
#pragma unroll
            for (int j = 0; j < 6; j++) acc[i][j] = 0.0f;

        for (int w = 0; w < HDIM; w++) {
            float a[6], bb[6];
#pragma unroll
            for (int j = 0; j < 6; j++) a[j]  = qs[(h0 + j) * PIT + w];
#pragma unroll
            for (int j = 0; j < 6; j++) bb[j] = ks[(g0 + j) * PIT + w];
#pragma unroll
            for (int i = 0; i < 6; i++)
#pragma unroll
                for (int j = 0; j < 6; j++)
                    acc[i][j] = fmaf(a[i], bb[j], acc[i][j]);
        }
#pragma unroll
        for (int i = 0; i < 6; i++)
#pragma unroll
            for (int j = 0; j < 6; j++)
                sc[(h0 + i) * PIT + g0 + j] = acc[i][j] * SCALE;
    }
    __syncthreads();

    {
        const int warp = tid >> 5, lane = tid & 31;
        for (int r = warp; r < HDIM; r += 8) {
            float m = -1e30f;
            for (int j = lane; j < HDIM; j += 32) m = fmaxf(m, sc[r * PIT + j]);
#pragma unroll
            for (int o = 16; o; o >>= 1) m = fmaxf(m, __shfl_xor_sync(0xffffffffu, m, o));
            float e[3]; float s = 0.0f;
            {
                int t = 0;
                for (int j = lane; j < HDIM; j += 32, t++) {
                    e[t] = __expf(sc[r * PIT + j] - m);
                    s += e[t];
                }
            }
#pragma unroll
            for (int o = 16; o; o >>= 1) s += __shfl_xor_sync(0xffffffffu, s, o);
            const float inv = 1.0f / s;
            {
                int t = 0;
                for (int j = lane; j < HDIM; j += 32, t++)
                    sc[r * PIT + j] = e[t] * inv;
            }
        }
    }
    __syncthreads();

    for (int i = tid; i < HW; i += 256) {
        int h = i / HDIM, w = i - h * HDIM;
        qs[h * PIT + w] = vg[i];
    }
    __syncthreads();

    {
        float acc[6][6];
#pragma unroll
        for (int i = 0; i < 6; i++)
#pragma unroll
            for (int j = 0; j < 6; j++) acc[i][j] = 0.0f;

        const int w0 = g0;
        for (int g = 0; g < HDIM; g++) {
            float a[6], bb[6];
#pragma unroll
            for (int j = 0; j < 6; j++) a[j]  = sc[(h0 + j) * PIT + g];
#pragma unroll
            for (int j = 0; j < 6; j++) bb[j] = qs[g * PIT + w0 + j];
#pragma unroll
            for (int i = 0; i < 6; i++)
#pragma unroll
                for (int j = 0; j < 6; j++)
                    acc[i][j] = fmaf(a[i], bb[j], acc[i][j]);
        }

        const float* fm = fmap + plane;
        float* og = out + plane;
#pragma unroll
        for (int i = 0; i < 6; i++)
#pragma unroll
            for (int j = 0; j < 6; j++) {
                int idx = (h0 + i) * HDIM + w0 + j;
                og[idx] = fm[idx] + acc[i][j];
            }
    }
}

// ---------------------------------------------------------------------------
// Launch.  Inputs: feature, feature_map, Wq, bq, Wk, bk, Wv, bv
// ---------------------------------------------------------------------------
extern "C" void kernel_launch(void* const* d_in, const int* in_sizes, int n_in,
                              void* d_out, int out_size)
{
    const float* feature = (const float*)d_in[0];
    const float* fmap    = (const float*)d_in[1];
    const float* Wq      = (const float*)d_in[2];
    const float* bq      = (const float*)d_in[3];
    const float* Wk      = (const float*)d_in[4];
    const float* bk      = (const float*)d_in[5];
    const float* Wv      = (const float*)d_in[6];
    const float* bv      = (const float*)d_in[7];
    float* out           = (float*)d_out;

    cudaFuncSetAttribute(proj_tc,
                         cudaFuncAttributeMaxDynamicSharedMemorySize, PROJ_SMEM);
    cudaFuncSetAttribute(attn_kernel,
                         cudaFuncAttributeMaxDynamicSharedMemorySize, ATTN_SMEM);

    dim3 g1(HW / 128, 6, BATCH);   // (72, 6, 16)
    proj_tc<<<g1, 256, PROJ_SMEM>>>(feature, Wq, bq, Wk, bk, Wv, bv);

    attn_kernel<<<BATCH * CHAN, 256, ATTN_SMEM>>>(fmap, out);
}